// round 7
// baseline (speedup 1.0000x reference)
#include <cuda_runtime.h>
#include <math.h>
#include <float.h>

#define NB    32
#define MROWS 100000
#define WC    64
#define RR    9
#define NIF   138
#define DIN   512
#define NBLK  55           // 55*32 = 1760 blocks ~ 2 waves of 148 SMs x 6 resident
#define CHUNK 1819         // ceil(100000/55)
#define NCAND (NBLK*8)     // 440 candidates per batch
#define NPOOL (256 + RR)   // block merge pool: 32 producers x 8 + 9 patch rows
#define NPART 4            // d-partition blocks per batch in iface GEMM

// -------- scratch (no allocation allowed) --------
__device__ float g_part[NB][NPART][NIF];
__device__ float g_q[NB][WC];            // read_query
__device__ float g_rows[NB][RR][WC];     // updated memory rows at rp
__device__ float g_cand_d[NB][NCAND];
__device__ int   g_cand_i[NB][NCAND];
__device__ int   g_tick_if[NB];          // zero-initialized; self-resetting tickets
__device__ int   g_tick_sc[NB];

__device__ __forceinline__ bool lt_pair(float d1, int i1, float d2, int i2) {
    return d1 < d2 || (d1 == d2 && i1 < i2);
}

__device__ __forceinline__ float dist8(float4 v0, float4 v1, float4 qa, float4 qb) {
    float dx, acc;
    dx = v0.x - qa.x; acc  = dx * dx;
    dx = v0.y - qa.y; acc += dx * dx;
    dx = v0.z - qa.z; acc += dx * dx;
    dx = v0.w - qa.w; acc += dx * dx;
    dx = v1.x - qb.x; acc += dx * dx;
    dx = v1.y - qb.y; acc += dx * dx;
    dx = v1.z - qb.z; acc += dx * dx;
    dx = v1.w - qb.w; acc += dx * dx;
    return acc;
}

// ================= Kernel 1: iface GEMM (fused partial + finish) =================
__global__ void k_iface(const float* __restrict__ xi, const float* __restrict__ Wm,
                        const float* __restrict__ b_lin, const float* __restrict__ usage,
                        const float* __restrict__ read_w, const float* __restrict__ rvec,
                        const int* __restrict__ rpos) {
    int b = blockIdx.y;
    int dbase = blockIdx.x * (DIN / NPART);
    __shared__ float sx[DIN / NPART];
    __shared__ float pp[4][NIF];
    __shared__ int slast;

    int tid = threadIdx.x;
    if (tid < DIN / NPART) sx[tid] = xi[b * DIN + dbase + tid];
    __syncthreads();

    int s = tid / NIF;
    int j = tid - s * NIF;
    if (s < 4) {
        int d0 = dbase + s * 32;
        float acc = 0.f;
        #pragma unroll
        for (int d = 0; d < 32; d++)
            acc = fmaf(sx[s * 32 + d], Wm[(d0 + d) * NIF + j], acc);
        pp[s][j] = acc;
    }
    __syncthreads();

    if (tid < NIF)
        g_part[b][blockIdx.x][tid] = pp[0][tid] + pp[1][tid] + pp[2][tid] + pp[3][tid];

    __threadfence();
    if (tid == 0) slast = (atomicAdd(&g_tick_if[b], 1) == NPART - 1);
    __syncthreads();
    if (!slast) return;
    if (tid == 0) g_tick_if[b] = 0;   // reset for next replay

    // ---- finish phase (only last block of batch b) ----
    __shared__ float sif[NIF];
    __shared__ float sww[RR];
    __shared__ float swv[WC];

    if (tid < NIF) {
        float acc = b_lin[tid];
        #pragma unroll
        for (int p = 0; p < NPART; p++) acc += __ldcg(&g_part[b][p][tid]);
        sif[tid] = acc;
        if (tid < WC) g_q[b][tid] = acc;                    // read_query
        if (tid >= WC && tid < 2 * WC) swv[tid - WC] = acc; // write_vector
    }
    __syncthreads();

    if (tid == 0) {
        float wg = 1.f / (1.f + expf(-sif[NIF - 1]));
        float rel[RR];
        float minu = INFINITY;
        #pragma unroll
        for (int k = 0; k < RR; k++) {
            int rp = rpos[b * RR + k];
            rel[k] = usage[(size_t)b * MROWS + rp];
            minu = fminf(minu, rel[k]);
        }
        #pragma unroll
        for (int k = 0; k < RR; k++) {
            float ig = 1.f / (1.f + expf(-sif[2 * WC + k]));
            float I  = (rel[k] == minu) ? 1.f : 0.f;
            sww[k] = wg * (ig * read_w[b * RR + k] + (1.f - ig) * I);
        }
    }
    __syncthreads();

    for (int t = tid; t < RR * WC; t += blockDim.x) {
        int k = t >> 6, w = t & 63;
        g_rows[b][k][w] = rvec[(b * RR + k) * WC + w] + sww[k] * swv[w];
    }
}

// ================= Kernel 2: streaming scan + fused final merge/gather =================
// COALESCED addressing: lane li reads floats [li*4, li*4+4) and [32+li*4, ...)
// of its row -> each LDG.128 covers 4 full 128B lines (no half-used sectors).
__global__ void __launch_bounds__(256, 6) k_scan(const float* __restrict__ mem,
                                                 const int* __restrict__ rpos,
                                                 float* __restrict__ out) {
    const int b = blockIdx.y;
    const int row0 = blockIdx.x * CHUNK;
    const int row_end = min(row0 + CHUNK, MROWS);
    const int lane = threadIdx.x & 31;
    const int warp = threadIdx.x >> 5;
    const int li = lane & 7;     // 8 lanes per row
    const int pg = lane >> 3;    // 4 rows per warp
    const unsigned gmask = 0xFFu << (pg * 8);
    const int prod = threadIdx.x >> 3;   // producer id (valid when li==0)

    __shared__ int srp[RR];
    __shared__ float sld[32][9];  // padded rows, conflict-free
    __shared__ int   slix[32][9];
    __shared__ float sd[NCAND];   // pool (265) then final merge (440)
    __shared__ int   si[NCAND];
    __shared__ int slast;
    __shared__ int sel[8];

    if (threadIdx.x < RR) srp[threadIdx.x] = rpos[b * RR + threadIdx.x];
    if (li == 0) {
        #pragma unroll
        for (int k = 0; k < 8; k++) { sld[prod][k] = INFINITY; slix[prod][k] = 0x7fffffff; }
    }
    __syncthreads();

    // q slices matching coalesced layout
    float4 qa = *(const float4*)&g_q[b][li * 4];
    float4 qb = *(const float4*)&g_q[b][32 + li * 4];

    float worst_d = INFINITY; int worst_i = 0x7fffffff;

    const float* base = mem + (size_t)b * MROWS * WC;
    int r = row0 + warp * 4 + pg;
    const float* pA = base + (size_t)r * WC + li * 4;

    auto insert_sh = [&](float cv, int ci) {
        bool stale = false;
        #pragma unroll
        for (int k = 0; k < RR; k++) stale |= (srp[k] == ci);
        if (stale) return;
        #pragma unroll
        for (int k = 0; k < 8; k++) {
            float dk = sld[prod][k]; int ik = slix[prod][k];
            bool sw = lt_pair(cv, ci, dk, ik);
            float nd = sw ? cv : dk; int ni = sw ? ci : ik;
            sld[prod][k] = nd; slix[prod][k] = ni;
            if (k == 7) { worst_d = nd; worst_i = ni; }
            if (sw) { cv = dk; ci = ik; }
        }
    };

    // unroll-by-2 pipeline: 4 float4 loads in flight per thread
    int nfull2 = (row_end - row0) >> 6;
    for (int it = 0; it < nfull2; ++it) {
        float4 a0 = __ldcs((const float4*)pA);
        float4 a1 = __ldcs((const float4*)(pA + 32));
        float4 c0 = __ldcs((const float4*)(pA + 32 * WC));
        float4 c1 = __ldcs((const float4*)(pA + 32 * WC + 32));
        float accA = dist8(a0, a1, qa, qb);
        float accB = dist8(c0, c1, qa, qb);
        accA += __shfl_xor_sync(0xffffffffu, accA, 1);
        accA += __shfl_xor_sync(0xffffffffu, accA, 2);
        accA += __shfl_xor_sync(0xffffffffu, accA, 4);
        accB += __shfl_xor_sync(0xffffffffu, accB, 1);
        accB += __shfl_xor_sync(0xffffffffu, accB, 2);
        accB += __shfl_xor_sync(0xffffffffu, accB, 4);
        if (li == 0) {
            if (lt_pair(accA, r, worst_d, worst_i))      insert_sh(accA, r);
            if (lt_pair(accB, r + 32, worst_d, worst_i)) insert_sh(accB, r + 32);
        }
        r += 64; pA += 64 * WC;
    }
    // remainder: up to 63 rows -> 2 guarded single iterations
    #pragma unroll
    for (int t = 0; t < 2; ++t) {
        if (r < row_end) {
            float4 a0 = __ldcs((const float4*)pA);
            float4 a1 = __ldcs((const float4*)(pA + 32));
            float acc = dist8(a0, a1, qa, qb);
            acc += __shfl_xor_sync(gmask, acc, 1);
            acc += __shfl_xor_sync(gmask, acc, 2);
            acc += __shfl_xor_sync(gmask, acc, 4);
            if (li == 0 && lt_pair(acc, r, worst_d, worst_i)) insert_sh(acc, r);
        }
        r += 32; pA += 32 * WC;
    }

    // producers copy their sorted-8 into the contiguous pool [0,256)
    if (li == 0) {
        #pragma unroll
        for (int k = 0; k < 8; k++) { sd[prod * 8 + k] = sld[prod][k]; si[prod * 8 + k] = slix[prod][k]; }
    }

    // warp 0: patch candidates for rp rows in this block's range (slots [256,265))
    if (warp == 0) {
        #pragma unroll
        for (int k = 0; k < RR; k++) {
            int rr = srp[k];
            bool use = (rr >= row0 && rr < row_end);
            #pragma unroll
            for (int k2 = k + 1; k2 < RR; k2++) use &= (srp[k2] != rr);  // last write wins
            float accv = 0.f;
            if (lane < 8) {
                float4 g0 = *(const float4*)&g_rows[b][k][lane * 4];
                float4 g1 = *(const float4*)&g_rows[b][k][32 + lane * 4];
                accv = dist8(g0, g1, qa, qb);
                accv += __shfl_xor_sync(0xFFu, accv, 1);
                accv += __shfl_xor_sync(0xFFu, accv, 2);
                accv += __shfl_xor_sync(0xFFu, accv, 4);
            }
            if (lane == 0) {
                sd[256 + k] = use ? accv : INFINITY;
                si[256 + k] = use ? rr   : 0x7fffffff;
            }
        }
    }
    __syncthreads();

    // merge pool (265 entries) -> block top-8 -> global candidate list
    if (threadIdx.x < 32) {
        int l = threadIdx.x;
        for (int s = 0; s < 8; s++) {
            float bd = INFINITY; int bi = 0x7fffffff; int bs = -1;
            for (int k = l; k < NPOOL; k += 32)
                if (lt_pair(sd[k], si[k], bd, bi)) { bd = sd[k]; bi = si[k]; bs = k; }
            #pragma unroll
            for (int off = 16; off; off >>= 1) {
                float od = __shfl_xor_sync(0xffffffffu, bd, off);
                int   oi = __shfl_xor_sync(0xffffffffu, bi, off);
                int   os = __shfl_xor_sync(0xffffffffu, bs, off);
                if (lt_pair(od, oi, bd, bi)) { bd = od; bi = oi; bs = os; }
            }
            if (l == 0) {
                g_cand_d[b][blockIdx.x * 8 + s] = bd;
                g_cand_i[b][blockIdx.x * 8 + s] = bi;
                if (bs >= 0) sd[bs] = INFINITY;
            }
            __syncwarp();
        }
    }

    // ---- ticket: last block of batch b performs the final merge + gather ----
    __threadfence();
    if (threadIdx.x == 0) slast = (atomicAdd(&g_tick_sc[b], 1) == NBLK - 1);
    __syncthreads();
    if (!slast) return;
    if (threadIdx.x == 0) g_tick_sc[b] = 0;   // reset for next replay

    for (int t = threadIdx.x; t < NCAND; t += blockDim.x) {
        sd[t] = __ldcg(&g_cand_d[b][t]);
        si[t] = __ldcg(&g_cand_i[b][t]);
    }
    __syncthreads();

    if (threadIdx.x < 32) {
        int l = threadIdx.x;
        for (int s = 0; s < 8; s++) {
            float bd = INFINITY; int bi = 0x7fffffff; int bs = -1;
            for (int k = l; k < NCAND; k += 32)
                if (lt_pair(sd[k], si[k], bd, bi)) { bd = sd[k]; bi = si[k]; bs = k; }
            #pragma unroll
            for (int off = 16; off; off >>= 1) {
                float od = __shfl_xor_sync(0xffffffffu, bd, off);
                int   oi = __shfl_xor_sync(0xffffffffu, bi, off);
                int   os = __shfl_xor_sync(0xffffffffu, bs, off);
                if (lt_pair(od, oi, bd, bi)) { bd = od; bi = oi; bs = os; }
            }
            if (l == 0) { sel[s] = bi; if (bs >= 0) sd[bs] = INFINITY; }
            __syncwarp();
        }
    }
    __syncthreads();

    for (int t = threadIdx.x; t < 8 * WC; t += blockDim.x) {
        int k = t >> 6, w = t & 63;
        int idx = sel[k];
        int src = -1;
        #pragma unroll
        for (int j = RR - 1; j >= 0; --j)
            if (src < 0 && srp[j] == idx) src = j;  // last write wins
        float v = (src >= 0) ? g_rows[b][src][w]
                             : __ldcg(&mem[((size_t)b * MROWS + idx) * WC + w]);
        out[(b * 8 + k) * WC + w] = v;
    }
}

// ================= launcher =================
extern "C" void kernel_launch(void* const* d_in, const int* in_sizes, int n_in,
                              void* d_out, int out_size) {
    const float* xi     = (const float*)d_in[0];
    const float* Wm     = (const float*)d_in[1];
    const float* b_lin  = (const float*)d_in[2];
    const float* mem    = (const float*)d_in[3];
    const float* usage  = (const float*)d_in[4];
    const float* read_w = (const float*)d_in[5];
    // d_in[6] write_weights: dead w.r.t. output
    const float* rvec   = (const float*)d_in[7];
    // d_in[8] last_used_mem: dead (only feeds rv[:,8,:] which is sliced off)
    const int*   rpos   = (const int*)d_in[9];
    // d_in[10] timestep: dead (only feeds usage update -> rw, never returned)
    float* out = (float*)d_out;

    k_iface<<<dim3(NPART, NB), 552>>>(xi, Wm, b_lin, usage, read_w, rvec, rpos);
    k_scan<<<dim3(NBLK, NB), 256>>>(mem, rpos, out);
}

// round 8
// speedup vs baseline: 1.5315x; 1.5315x over previous
#include <cuda_runtime.h>
#include <math.h>
#include <float.h>

#define NB    32
#define MROWS 100000
#define WC    64
#define RR    9
#define NIF   138
#define DIN   512
#define NBLK  37           // 37*32 = 1184 blocks = 2 waves of 592 (148 SMs x 4)
#define CHUNK 2703         // ceil(100000/37)
#define NCAND (NBLK*8)     // 296 candidates per batch
#define NPOOL (256 + RR)   // block merge pool: 32 producers x 8 + 9 patch rows
#define NPART 4            // d-partition blocks per batch in iface GEMM

// -------- scratch (no allocation allowed) --------
__device__ float g_part[NB][NPART][NIF];
__device__ float g_q[NB][WC];            // read_query
__device__ float g_rows[NB][RR][WC];     // updated memory rows at rp
__device__ float g_cand_d[NB][NCAND];
__device__ int   g_cand_i[NB][NCAND];
__device__ int   g_tick_if[NB];          // zero-initialized; self-resetting tickets
__device__ int   g_tick_sc[NB];

__device__ __forceinline__ bool lt_pair(float d1, int i1, float d2, int i2) {
    return d1 < d2 || (d1 == d2 && i1 < i2);
}

__device__ __forceinline__ float dist8(float4 v0, float4 v1, float4 qa, float4 qb) {
    float dx, acc;
    dx = v0.x - qa.x; acc  = dx * dx;
    dx = v0.y - qa.y; acc += dx * dx;
    dx = v0.z - qa.z; acc += dx * dx;
    dx = v0.w - qa.w; acc += dx * dx;
    dx = v1.x - qb.x; acc += dx * dx;
    dx = v1.y - qb.y; acc += dx * dx;
    dx = v1.z - qb.z; acc += dx * dx;
    dx = v1.w - qb.w; acc += dx * dx;
    return acc;
}

// insert with stale-row exclusion; all-register, predicated (no shared state).
__device__ __forceinline__ void insert8x(float cv, int ci, float (&ld)[8], int (&lix)[8],
                                         const int* __restrict__ srp) {
    if (lt_pair(cv, ci, ld[7], lix[7])) {
        bool stale = false;
        #pragma unroll
        for (int k = 0; k < RR; k++) stale |= (srp[k] == ci);
        if (!stale) {
            #pragma unroll
            for (int k = 0; k < 8; k++) {
                bool sw = lt_pair(cv, ci, ld[k], lix[k]);
                float td = ld[k]; int ti = lix[k];
                if (sw) { ld[k] = cv; lix[k] = ci; cv = td; ci = ti; }
            }
        }
    }
}

// ================= Kernel 1: iface GEMM (fused partial + finish) =================
__global__ void k_iface(const float* __restrict__ xi, const float* __restrict__ Wm,
                        const float* __restrict__ b_lin, const float* __restrict__ usage,
                        const float* __restrict__ read_w, const float* __restrict__ rvec,
                        const int* __restrict__ rpos) {
    int b = blockIdx.y;
    int dbase = blockIdx.x * (DIN / NPART);
    __shared__ float sx[DIN / NPART];
    __shared__ float pp[4][NIF];
    __shared__ int slast;

    int tid = threadIdx.x;
    if (tid < DIN / NPART) sx[tid] = xi[b * DIN + dbase + tid];
    __syncthreads();

    int s = tid / NIF;
    int j = tid - s * NIF;
    if (s < 4) {
        int d0 = dbase + s * 32;
        float acc = 0.f;
        #pragma unroll
        for (int d = 0; d < 32; d++)
            acc = fmaf(sx[s * 32 + d], Wm[(d0 + d) * NIF + j], acc);
        pp[s][j] = acc;
    }
    __syncthreads();

    if (tid < NIF)
        g_part[b][blockIdx.x][tid] = pp[0][tid] + pp[1][tid] + pp[2][tid] + pp[3][tid];

    __threadfence();
    if (tid == 0) slast = (atomicAdd(&g_tick_if[b], 1) == NPART - 1);
    __syncthreads();
    if (!slast) return;
    if (tid == 0) g_tick_if[b] = 0;   // reset for next replay

    // ---- finish phase (only last block of batch b) ----
    __shared__ float sif[NIF];
    __shared__ float sww[RR];
    __shared__ float swv[WC];

    if (tid < NIF) {
        float acc = b_lin[tid];
        #pragma unroll
        for (int p = 0; p < NPART; p++) acc += __ldcg(&g_part[b][p][tid]);
        sif[tid] = acc;
        if (tid < WC) g_q[b][tid] = acc;                    // read_query
        if (tid >= WC && tid < 2 * WC) swv[tid - WC] = acc; // write_vector
    }
    __syncthreads();

    if (tid == 0) {
        float wg = 1.f / (1.f + expf(-sif[NIF - 1]));
        float rel[RR];
        float minu = INFINITY;
        #pragma unroll
        for (int k = 0; k < RR; k++) {
            int rp = rpos[b * RR + k];
            rel[k] = usage[(size_t)b * MROWS + rp];
            minu = fminf(minu, rel[k]);
        }
        #pragma unroll
        for (int k = 0; k < RR; k++) {
            float ig = 1.f / (1.f + expf(-sif[2 * WC + k]));
            float I  = (rel[k] == minu) ? 1.f : 0.f;
            sww[k] = wg * (ig * read_w[b * RR + k] + (1.f - ig) * I);
        }
    }
    __syncthreads();

    for (int t = tid; t < RR * WC; t += blockDim.x) {
        int k = t >> 6, w = t & 63;
        g_rows[b][k][w] = rvec[(b * RR + k) * WC + w] + sww[k] * swv[w];
    }
}

// ================= Kernel 2: streaming scan + fused final merge/gather =================
// R5 structure (register top-8, occ 4) with CONTIGUOUS addressing: lane li reads
// floats [li*4, li*4+4) and [32+li*4, 32+li*4+4) -> each LDG.128 touches 4 lines.
__global__ void __launch_bounds__(256, 4) k_scan(const float* __restrict__ mem,
                                                 const int* __restrict__ rpos,
                                                 float* __restrict__ out) {
    const int b = blockIdx.y;
    const int row0 = blockIdx.x * CHUNK;
    const int row_end = min(row0 + CHUNK, MROWS);
    const int lane = threadIdx.x & 31;
    const int warp = threadIdx.x >> 5;
    const int li = lane & 7;     // 8 lanes per row
    const int pg = lane >> 3;    // 4 rows per warp
    const unsigned gmask = 0xFFu << (pg * 8);

    __shared__ int srp[RR];
    __shared__ float sd[NCAND];   // pool (265) then final merge (296)
    __shared__ int   si[NCAND];
    __shared__ int slast;
    __shared__ int sel[8];
    if (threadIdx.x < RR) srp[threadIdx.x] = rpos[b * RR + threadIdx.x];
    __syncthreads();

    // q slices matching contiguous layout
    float4 qa = *(const float4*)&g_q[b][li * 4];
    float4 qb = *(const float4*)&g_q[b][32 + li * 4];

    float ld[8]; int lix[8];
    #pragma unroll
    for (int k = 0; k < 8; k++) { ld[k] = INFINITY; lix[k] = 0x7fffffff; }

    const float* base = mem + (size_t)b * MROWS * WC;
    int r = row0 + warp * 4 + pg;
    const float* pA = base + (size_t)r * WC + li * 4;

    // unroll-by-2 pipeline: 4 float4 loads in flight per thread
    int nfull2 = (row_end - row0) >> 6;
    for (int it = 0; it < nfull2; ++it) {
        float4 a0 = __ldcs((const float4*)pA);
        float4 a1 = __ldcs((const float4*)(pA + 32));
        float4 c0 = __ldcs((const float4*)(pA + 32 * WC));
        float4 c1 = __ldcs((const float4*)(pA + 32 * WC + 32));
        float accA = dist8(a0, a1, qa, qb);
        float accB = dist8(c0, c1, qa, qb);
        accA += __shfl_xor_sync(0xffffffffu, accA, 1);
        accA += __shfl_xor_sync(0xffffffffu, accA, 2);
        accA += __shfl_xor_sync(0xffffffffu, accA, 4);
        accB += __shfl_xor_sync(0xffffffffu, accB, 1);
        accB += __shfl_xor_sync(0xffffffffu, accB, 2);
        accB += __shfl_xor_sync(0xffffffffu, accB, 4);
        if (li == 0) {
            insert8x(accA, r, ld, lix, srp);
            insert8x(accB, r + 32, ld, lix, srp);
        }
        r += 64; pA += 64 * WC;
    }
    // remainder: up to 63 rows -> 2 guarded single iterations
    #pragma unroll
    for (int t = 0; t < 2; ++t) {
        if (r < row_end) {
            float4 a0 = __ldcs((const float4*)pA);
            float4 a1 = __ldcs((const float4*)(pA + 32));
            float acc = dist8(a0, a1, qa, qb);
            acc += __shfl_xor_sync(gmask, acc, 1);
            acc += __shfl_xor_sync(gmask, acc, 2);
            acc += __shfl_xor_sync(gmask, acc, 4);
            if (li == 0) insert8x(acc, r, ld, lix, srp);
        }
        r += 32; pA += 32 * WC;
    }

    // producers dump sorted-8 to pool slots [0,256)
    if (li == 0) {
        int slot = threadIdx.x >> 3;
        #pragma unroll
        for (int k = 0; k < 8; k++) { sd[slot * 8 + k] = ld[k]; si[slot * 8 + k] = lix[k]; }
    }

    // warp 0: patch candidates for rp rows in this block's range (slots [256,265))
    if (warp == 0) {
        #pragma unroll
        for (int k = 0; k < RR; k++) {
            int rr = srp[k];
            bool use = (rr >= row0 && rr < row_end);
            #pragma unroll
            for (int k2 = k + 1; k2 < RR; k2++) use &= (srp[k2] != rr);  // last write wins
            float accv = 0.f;
            if (lane < 8) {
                float4 g0 = *(const float4*)&g_rows[b][k][lane * 4];
                float4 g1 = *(const float4*)&g_rows[b][k][32 + lane * 4];
                accv = dist8(g0, g1, qa, qb);
                accv += __shfl_xor_sync(0xFFu, accv, 1);
                accv += __shfl_xor_sync(0xFFu, accv, 2);
                accv += __shfl_xor_sync(0xFFu, accv, 4);
            }
            if (lane == 0) {
                sd[256 + k] = use ? accv : INFINITY;
                si[256 + k] = use ? rr   : 0x7fffffff;
            }
        }
    }
    __syncthreads();

    // merge pool (265 entries) -> block top-8 -> global candidate list
    if (threadIdx.x < 32) {
        int l = threadIdx.x;
        for (int s = 0; s < 8; s++) {
            float bd = INFINITY; int bi = 0x7fffffff; int bs = -1;
            for (int k = l; k < NPOOL; k += 32)
                if (lt_pair(sd[k], si[k], bd, bi)) { bd = sd[k]; bi = si[k]; bs = k; }
            #pragma unroll
            for (int off = 16; off; off >>= 1) {
                float od = __shfl_xor_sync(0xffffffffu, bd, off);
                int   oi = __shfl_xor_sync(0xffffffffu, bi, off);
                int   os = __shfl_xor_sync(0xffffffffu, bs, off);
                if (lt_pair(od, oi, bd, bi)) { bd = od; bi = oi; bs = os; }
            }
            if (l == 0) {
                g_cand_d[b][blockIdx.x * 8 + s] = bd;
                g_cand_i[b][blockIdx.x * 8 + s] = bi;
                if (bs >= 0) sd[bs] = INFINITY;
            }
            __syncwarp();
        }
    }

    // ---- ticket: last block of batch b performs the final merge + gather ----
    __threadfence();
    if (threadIdx.x == 0) slast = (atomicAdd(&g_tick_sc[b], 1) == NBLK - 1);
    __syncthreads();
    if (!slast) return;
    if (threadIdx.x == 0) g_tick_sc[b] = 0;   // reset for next replay

    for (int t = threadIdx.x; t < NCAND; t += blockDim.x) {
        sd[t] = __ldcg(&g_cand_d[b][t]);
        si[t] = __ldcg(&g_cand_i[b][t]);
    }
    __syncthreads();

    if (threadIdx.x < 32) {
        int l = threadIdx.x;
        for (int s = 0; s < 8; s++) {
            float bd = INFINITY; int bi = 0x7fffffff; int bs = -1;
            for (int k = l; k < NCAND; k += 32)
                if (lt_pair(sd[k], si[k], bd, bi)) { bd = sd[k]; bi = si[k]; bs = k; }
            #pragma unroll
            for (int off = 16; off; off >>= 1) {
                float od = __shfl_xor_sync(0xffffffffu, bd, off);
                int   oi = __shfl_xor_sync(0xffffffffu, bi, off);
                int   os = __shfl_xor_sync(0xffffffffu, bs, off);
                if (lt_pair(od, oi, bd, bi)) { bd = od; bi = oi; bs = os; }
            }
            if (l == 0) { sel[s] = bi; if (bs >= 0) sd[bs] = INFINITY; }
            __syncwarp();
        }
    }
    __syncthreads();

    for (int t = threadIdx.x; t < 8 * WC; t += blockDim.x) {
        int k = t >> 6, w = t & 63;
        int idx = sel[k];
        int src = -1;
        #pragma unroll
        for (int j = RR - 1; j >= 0; --j)
            if (src < 0 && srp[j] == idx) src = j;  // last write wins
        float v = (src >= 0) ? g_rows[b][src][w]
                             : __ldcg(&mem[((size_t)b * MROWS + idx) * WC + w]);
        out[(b * 8 + k) * WC + w] = v;
    }
}

// ================= launcher =================
extern "C" void kernel_launch(void* const* d_in, const int* in_sizes, int n_in,
                              void* d_out, int out_size) {
    const float* xi     = (const float*)d_in[0];
    const float* Wm     = (const float*)d_in[1];
    const float* b_lin  = (const float*)d_in[2];
    const float* mem    = (const float*)d_in[3];
    const float* usage  = (const float*)d_in[4];
    const float* read_w = (const float*)d_in[5];
    // d_in[6] write_weights: dead w.r.t. output
    const float* rvec   = (const float*)d_in[7];
    // d_in[8] last_used_mem: dead (only feeds rv[:,8,:] which is sliced off)
    const int*   rpos   = (const int*)d_in[9];
    // d_in[10] timestep: dead (only feeds usage update -> rw, never returned)
    float* out = (float*)d_out;

    k_iface<<<dim3(NPART, NB), 552>>>(xi, Wm, b_lin, usage, read_w, rvec, rpos);
    k_scan<<<dim3(NBLK, NB), 256>>>(mem, rpos, out);
}